// round 1
// baseline (speedup 1.0000x reference)
#include <cuda_runtime.h>
#include <cstdint>
#include <cstddef>

// ---------------- problem constants ----------------
#define BB 16
#define CC 64
#define HH 64
#define WW 64
#define HWN 4096         // H*W
#define KC 16            // clusters
#define FF 576           // C*9
#define OO 64
#define RR 8
#define MLPD 32

// ---------------- device scratch (static, allowed) ----------------
__device__ float g_patches[BB * HWN * FF];     // 151 MB  [b][n][f]
__device__ float g_kernels[BB * KC * FF * OO]; // 37.7 MB [b][k][f][o]
__device__ float g_centers[BB * KC * FF];      // raw sums
__device__ float g_counts[BB * KC];
__device__ int   g_offs[BB * 17];
__device__ int   g_cur[BB * KC];
__device__ int   g_perm[BB * HWN];
__device__ float g_lowrank[BB * KC * RR];
__device__ float g_biasv[BB * KC * OO];

// ---------------- helpers ----------------
__device__ __forceinline__ uint32_t smem_u32(const void* p) {
    return (uint32_t)__cvta_generic_to_shared(p);
}
#define CP16(dst, src) asm volatile("cp.async.cg.shared.global [%0], [%1], 16;" :: "r"(dst), "l"(src))
#define CP_COMMIT()    asm volatile("cp.async.commit_group;")
#define CP_WAIT(n)     asm volatile("cp.async.wait_group %0;" :: "n"(n))

__device__ __forceinline__ unsigned long long pack2(float v) {
    unsigned long long r;
    uint32_t u = __float_as_uint(v);
    asm("mov.b64 %0, {%1, %1};" : "=l"(r) : "r"(u));
    return r;
}
#define FMA2(d, a, b, c) asm("fma.rn.f32x2 %0, %1, %2, %3;" : "=l"(d) : "l"(a), "l"(b), "l"(c))

// ================= K1: unfold (build patches, coalesced) =================
// grid (64 y, 16 b), block 256, dyn smem = 64*195*4 = 49920 B
__global__ void unfold_kernel(const float* __restrict__ x) {
    extern __shared__ float sm[];   // [c][i][xx] stride c*195 + i*65 + xx
    const int y = blockIdx.x, b = blockIdx.y;

    for (int idx = threadIdx.x; idx < 64 * 3 * 64; idx += 256) {
        int c = idx / 192;
        int r = idx - c * 192;
        int i = r >> 6;
        int xx = r & 63;
        int yy = y + i - 1;
        float v = (yy >= 0 && yy < 64) ? x[(((size_t)(b * 64 + c)) * 64 + yy) * 64 + xx] : 0.f;
        sm[c * 195 + i * 65 + xx] = v;
    }
    __syncthreads();

    const int nbase = b * HWN + y * 64;
    for (int e = threadIdx.x; e < 64 * 144; e += 256) {
        int xq = e / 144;
        int f4 = e - xq * 144;
        int f = f4 << 2;
        float vq[4];
#pragma unroll
        for (int q = 0; q < 4; q++) {
            int ff = f + q;
            int c = ff / 9;
            int tap = ff - c * 9;
            int i = tap / 3;
            int j = tap - i * 3;
            int xx = xq + j - 1;
            vq[q] = (xx >= 0 && xx < 64) ? sm[c * 195 + i * 65 + xx] : 0.f;
        }
        float4 v = make_float4(vq[0], vq[1], vq[2], vq[3]);
        *reinterpret_cast<float4*>(&g_patches[(size_t)(nbase + xq) * FF + f]) = v;
    }
}

// ================= K2: counts + offsets + cursor init =================
__global__ void counts_kernel(const int* __restrict__ labels) { // grid 16, block 256
    __shared__ int cnt[KC];
    const int b = blockIdx.x;
    if (threadIdx.x < KC) cnt[threadIdx.x] = 0;
    __syncthreads();
    for (int n = threadIdx.x; n < HWN; n += 256)
        atomicAdd(&cnt[labels[b * HWN + n]], 1);
    __syncthreads();
    if (threadIdx.x == 0) {
        int off = 0;
        for (int k = 0; k < KC; k++) {
            g_offs[b * 17 + k] = off;
            g_cur[b * KC + k] = off;
            g_counts[b * KC + k] = (float)cnt[k];
            off += cnt[k];
        }
        g_offs[b * 17 + 16] = off;
    }
}

// ================= K3: scatter pixel indices by cluster =================
__global__ void scatter_kernel(const int* __restrict__ labels) { // grid 16, block 256
    const int b = blockIdx.x;
    for (int n = threadIdx.x; n < HWN; n += 256) {
        int k = labels[b * HWN + n];
        int pos = atomicAdd(&g_cur[b * KC + k], 1);
        g_perm[b * HWN + pos] = n;
    }
}

// ================= K4: cluster centers (raw sums) =================
// grid (64 c, 16 b), block 256
__global__ void centers_kernel(const float* __restrict__ x, const int* __restrict__ labels) {
    __shared__ float xs[HWN];
    __shared__ float acc[KC * 9];
    const int c = blockIdx.x, b = blockIdx.y;
    if (threadIdx.x < KC * 9) acc[threadIdx.x] = 0.f;
    for (int i = threadIdx.x; i < HWN; i += 256)
        xs[i] = x[((size_t)(b * 64 + c)) * HWN + i];
    __syncthreads();

    for (int n = threadIdx.x; n < HWN; n += 256) {
        int k = labels[b * HWN + n];
        int y = n >> 6, xq = n & 63;
#pragma unroll
        for (int i = 0; i < 3; i++) {
            int yy = y + i - 1;
            if (yy < 0 || yy >= 64) continue;
#pragma unroll
            for (int j = 0; j < 3; j++) {
                int xx = xq + j - 1;
                if (xx < 0 || xx >= 64) continue;
                atomicAdd(&acc[k * 9 + i * 3 + j], xs[yy * 64 + xx]);
            }
        }
    }
    __syncthreads();
    if (threadIdx.x < KC * 9) {
        int k = threadIdx.x / 9, tap = threadIdx.x - k * 9;
        g_centers[(size_t)(b * KC + k) * FF + c * 9 + tap] = acc[threadIdx.x];
    }
}

// ================= K5: tiny MLPs per (b,k) =================
// grid 256 (= b*16+k), block 64
__global__ void mlp_kernel(const float* __restrict__ lr_w1, const float* __restrict__ lr_b1,
                           const float* __restrict__ lr_w2, const float* __restrict__ lr_b2,
                           const float* __restrict__ lr_w3, const float* __restrict__ lr_b3,
                           const float* __restrict__ bw1,   const float* __restrict__ bb1,
                           const float* __restrict__ bw2,   const float* __restrict__ bb2) {
    __shared__ float cs[FF], h1[MLPD], h2[MLPD], t1[MLPD];
    const int bk = blockIdx.x;
    const int j = threadIdx.x;
    const float cntd = g_counts[bk] + 1e-6f;
    for (int f = j; f < FF; f += 64) cs[f] = g_centers[(size_t)bk * FF + f] / cntd;
    __syncthreads();

    if (j < MLPD) {
        float s = lr_b1[j];
        float s2 = bb1[j];
        for (int f = 0; f < FF; f++) {
            float cv = cs[f];
            s  += cv * lr_w1[f * MLPD + j];
            s2 += cv * bw1[f * MLPD + j];
        }
        h1[j] = fmaxf(s, 0.f);
        t1[j] = fmaxf(s2, 0.f);
    }
    __syncthreads();
    if (j < MLPD) {
        float s = lr_b2[j];
        for (int i = 0; i < MLPD; i++) s += h1[i] * lr_w2[i * MLPD + j];
        h2[j] = fmaxf(s, 0.f);
    }
    __syncthreads();
    if (j < RR) {
        float s = lr_b3[j];
        for (int i = 0; i < MLPD; i++) s += h2[i] * lr_w3[i * RR + j];
        g_lowrank[bk * RR + j] = s;
    }
    {
        float s = bb2[j];
        for (int i = 0; i < MLPD; i++) s += t1[i] * bw2[i * OO + j];
        g_biasv[bk * OO + j] = s;
    }
}

// ================= K6: fabricate per-cluster kernels =================
// kernels[bk][f][o] = sum_r lowrank[bk][r] * base[r][f][o]
// grid (36 f-chunks of 16 rows, 8 bk-groups of 32), block 256
__global__ void buildk_kernel(const float* __restrict__ base) {
    __shared__ float bs[RR][16 * 64];   // 32 KB
    __shared__ float lrs[32][RR];
    const int fb = blockIdx.x, gb = blockIdx.y;
    const int f0 = fb * 16;

    for (int idx = threadIdx.x; idx < RR * 1024; idx += 256) {
        int r = idx >> 10;
        int e = idx & 1023;
        bs[r][e] = base[((size_t)(r * FF + f0 + (e >> 6))) * OO + (e & 63)];
    }
    for (int idx = threadIdx.x; idx < 32 * RR; idx += 256)
        lrs[idx >> 3][idx & 7] = g_lowrank[(gb * 32 + (idx >> 3)) * RR + (idx & 7)];
    __syncthreads();

    for (int bi = 0; bi < 32; bi++) {
        const int bk = gb * 32 + bi;
        float l[RR];
#pragma unroll
        for (int r = 0; r < RR; r++) l[r] = lrs[bi][r];
#pragma unroll
        for (int s = 0; s < 4; s++) {
            int e = threadIdx.x + (s << 8);
            float v = 0.f;
#pragma unroll
            for (int r = 0; r < RR; r++) v += l[r] * bs[r][e];
            g_kernels[(size_t)bk * (FF * OO) + f0 * OO + e] = v;
        }
    }
}

// ================= K7: grouped GEMM (fp32x2 packed FMA) =================
// tile M=128, N=64, K chunks of 64. grid (256 bk, 16 m-tiles), block 256
// dyn smem: A[2][128][68] (69632 B) + B[2][64][64] (32768 B) + rows[128] (512 B) = 102912 B
__global__ void __launch_bounds__(256, 2) gemm_kernel(float* __restrict__ out) {
    extern __shared__ char smraw[];
    float* Asm = (float*)smraw;                        // stride 68 per row
    float* Bsm = (float*)(smraw + 69632);
    int*  rows = (int*)(smraw + 69632 + 32768);

    const int bk = blockIdx.x;
    const int b = bk >> 4;
    const int off = g_offs[bk + b];        // b*17 + k
    const int end = g_offs[bk + b + 1];
    const int m0 = blockIdx.y << 7;
    if (off + m0 >= end) return;
    const int nk = end - off;
    const int tid = threadIdx.x;

    if (tid < 128) {
        int i = m0 + tid;
        rows[tid] = g_perm[(b << 12) + off + (i < nk ? i : 0)];
    }
    __syncthreads();

    const float* __restrict__ pb = g_patches + ((size_t)b << 12) * FF;
    const float* __restrict__ kb = g_kernels + (size_t)bk * (FF * OO);

    unsigned long long acc[16];
#pragma unroll
    for (int i = 0; i < 16; i++) acc[i] = 0ull;

    const int tx = tid & 7, ty = tid >> 3;

    // prologue: chunk 0
    {
#pragma unroll
        for (int s = 0; s < 8; s++) {
            int cid = tid + (s << 8);
            int row = cid >> 4, seg = (cid & 15) << 2;
            CP16(smem_u32(Asm + row * 68 + seg), pb + (size_t)rows[row] * FF + seg);
        }
#pragma unroll
        for (int s = 0; s < 4; s++) {
            int cid = (tid + (s << 8)) << 2;
            CP16(smem_u32(Bsm + cid), kb + cid);
        }
        CP_COMMIT();
    }

    for (int c = 0; c < 9; c++) {
        const int buf = c & 1;
        if (c < 8) {
            const int nb = buf ^ 1;
            const int kc = (c + 1) << 6;
#pragma unroll
            for (int s = 0; s < 8; s++) {
                int cid = tid + (s << 8);
                int row = cid >> 4, seg = (cid & 15) << 2;
                CP16(smem_u32(Asm + nb * 8704 + row * 68 + seg),
                     pb + (size_t)rows[row] * FF + kc + seg);
            }
#pragma unroll
            for (int s = 0; s < 4; s++) {
                int cid = (tid + (s << 8)) << 2;
                CP16(smem_u32(Bsm + nb * 4096 + cid), kb + (size_t)kc * 64 + cid);
            }
            CP_COMMIT();
            CP_WAIT(1);
        } else {
            CP_WAIT(0);
        }
        __syncthreads();

        const float* Ab = Asm + buf * 8704 + (ty << 2) * 68;
        const float* Bb = Bsm + buf * 4096 + (tx << 3);
#pragma unroll 8
        for (int kk = 0; kk < 64; kk++) {
            unsigned long long pa[4];
            pa[0] = pack2(Ab[kk]);
            pa[1] = pack2(Ab[kk + 68]);
            pa[2] = pack2(Ab[kk + 136]);
            pa[3] = pack2(Ab[kk + 204]);
            ulonglong2 q0 = *reinterpret_cast<const ulonglong2*>(Bb + (kk << 6));
            ulonglong2 q1 = *reinterpret_cast<const ulonglong2*>(Bb + (kk << 6) + 4);
            unsigned long long bbv[4] = {q0.x, q0.y, q1.x, q1.y};
#pragma unroll
            for (int j = 0; j < 4; j++) {
#pragma unroll
                for (int p = 0; p < 4; p++) {
                    FMA2(acc[(j << 2) + p], pa[j], bbv[p], acc[(j << 2) + p]);
                }
            }
        }
        __syncthreads();
    }

    // epilogue: add cluster bias, scatter to out[b][o][n]
    float bias[8];
#pragma unroll
    for (int q = 0; q < 8; q++) bias[q] = g_biasv[(bk << 6) + (tx << 3) + q];

#pragma unroll
    for (int j = 0; j < 4; j++) {
        int i = m0 + (ty << 2) + j;
        if (i < nk) {
            int n = rows[(ty << 2) + j];
#pragma unroll
            for (int p = 0; p < 4; p++) {
                uint32_t lo, hi;
                asm("mov.b64 {%0,%1}, %2;" : "=r"(lo), "=r"(hi) : "l"(acc[(j << 2) + p]));
                int o = (tx << 3) + (p << 1);
                out[(size_t)((b << 6) + o) * HWN + n]     = __uint_as_float(lo) + bias[(p << 1)];
                out[(size_t)((b << 6) + o + 1) * HWN + n] = __uint_as_float(hi) + bias[(p << 1) + 1];
            }
        }
    }
}

// ================= launch =================
extern "C" void kernel_launch(void* const* d_in, const int* in_sizes, int n_in,
                              void* d_out, int out_size) {
    const float* x      = (const float*)d_in[0];
    const int*   labels = (const int*)d_in[1];
    const float* lr_w1  = (const float*)d_in[2];
    const float* lr_b1  = (const float*)d_in[3];
    const float* lr_w2  = (const float*)d_in[4];
    const float* lr_b2  = (const float*)d_in[5];
    const float* lr_w3  = (const float*)d_in[6];
    const float* lr_b3  = (const float*)d_in[7];
    const float* base   = (const float*)d_in[8];
    const float* bw1    = (const float*)d_in[9];
    const float* bb1    = (const float*)d_in[10];
    const float* bw2    = (const float*)d_in[11];
    const float* bb2    = (const float*)d_in[12];
    float* out = (float*)d_out;

    cudaFuncSetAttribute(unfold_kernel, cudaFuncAttributeMaxDynamicSharedMemorySize, 50176);
    cudaFuncSetAttribute(gemm_kernel,   cudaFuncAttributeMaxDynamicSharedMemorySize, 102912);

    unfold_kernel<<<dim3(64, 16), 256, 49920>>>(x);
    counts_kernel<<<16, 256>>>(labels);
    scatter_kernel<<<16, 256>>>(labels);
    centers_kernel<<<dim3(64, 16), 256>>>(x, labels);
    mlp_kernel<<<256, 64>>>(lr_w1, lr_b1, lr_w2, lr_b2, lr_w3, lr_b3, bw1, bb1, bw2, bb2);
    buildk_kernel<<<dim3(36, 8), 256>>>(base);
    gemm_kernel<<<dim3(256, 16), 256, 102912>>>(out);
}

// round 2
// speedup vs baseline: 1.3955x; 1.3955x over previous
#include <cuda_runtime.h>
#include <cstdint>
#include <cstddef>

// ---------------- problem constants ----------------
#define BB 16
#define HWN 4096         // H*W
#define KC 16            // clusters
#define FF 576           // C*9
#define OO 64
#define RR 8
#define MLPD 32

// ---------------- device scratch (static, allowed) ----------------
__device__ float g_patches[BB * HWN * FF];     // 151 MB  [b][n][f]
__device__ float g_kernels[BB * KC * FF * OO]; // 37.7 MB [b][k][f][o]
__device__ int   g_offs[BB * 17];
__device__ int   g_perm[BB * HWN];
__device__ float g_lowrank[BB * KC * RR];
__device__ float g_biasv[BB * KC * OO];

// ---------------- helpers ----------------
__device__ __forceinline__ uint32_t smem_u32(const void* p) {
    return (uint32_t)__cvta_generic_to_shared(p);
}
#define CP16(dst, src) asm volatile("cp.async.cg.shared.global [%0], [%1], 16;" :: "r"(dst), "l"(src))
#define CP_COMMIT()    asm volatile("cp.async.commit_group;")
#define CP_WAIT(n)     asm volatile("cp.async.wait_group %0;" :: "n"(n))

__device__ __forceinline__ unsigned long long pack2(float v) {
    unsigned long long r;
    uint32_t u = __float_as_uint(v);
    asm("mov.b64 %0, {%1, %1};" : "=l"(r) : "r"(u));
    return r;
}
#define FMA2(d, a, b, c) asm("fma.rn.f32x2 %0, %1, %2, %3;" : "=l"(d) : "l"(a), "l"(b), "l"(c))

// ================= K1: unfold (build patches, coalesced) =================
// grid (64 y, 16 b), block 256, dyn smem = 64*195*4 = 49920 B
__global__ void unfold_kernel(const float* __restrict__ x) {
    extern __shared__ float sm[];   // [c][i][xx] stride c*195 + i*65 + xx
    const int y = blockIdx.x, b = blockIdx.y;

    for (int idx = threadIdx.x; idx < 64 * 3 * 64; idx += 256) {
        int c = idx / 192;
        int r = idx - c * 192;
        int i = r >> 6;
        int xx = r & 63;
        int yy = y + i - 1;
        float v = (yy >= 0 && yy < 64) ? x[(((size_t)(b * 64 + c)) * 64 + yy) * 64 + xx] : 0.f;
        sm[c * 195 + i * 65 + xx] = v;
    }
    __syncthreads();

    const int nbase = b * HWN + y * 64;
    for (int e = threadIdx.x; e < 64 * 144; e += 256) {
        int xq = e / 144;
        int f4 = e - xq * 144;
        int f = f4 << 2;
        float vq[4];
#pragma unroll
        for (int q = 0; q < 4; q++) {
            int ff = f + q;
            int c = ff / 9;
            int tap = ff - c * 9;
            int i = tap / 3;
            int j = tap - i * 3;
            int xx = xq + j - 1;
            vq[q] = (xx >= 0 && xx < 64) ? sm[c * 195 + i * 65 + xx] : 0.f;
        }
        float4 v = make_float4(vq[0], vq[1], vq[2], vq[3]);
        *reinterpret_cast<float4*>(&g_patches[(size_t)(nbase + xq) * FF + f]) = v;
    }
}

// ================= K2: counts + prefix + scatter (warp-aggregated atomics) =================
// grid 16 (batch), block 256
__global__ void count_scatter_kernel(const int* __restrict__ labels) {
    __shared__ int cnt[KC];
    __shared__ int offs[KC];
    const int b = blockIdx.x;
    const int lane = threadIdx.x & 31;
    if (threadIdx.x < KC) cnt[threadIdx.x] = 0;
    __syncthreads();

    for (int n = threadIdx.x; n < HWN; n += 256) {
        int k = labels[b * HWN + n];
        unsigned mask = __match_any_sync(0xffffffffu, k);
        if (lane == (__ffs(mask) - 1)) atomicAdd(&cnt[k], __popc(mask));
    }
    __syncthreads();
    if (threadIdx.x == 0) {
        int off = 0;
        for (int k = 0; k < KC; k++) {
            g_offs[b * 17 + k] = off;
            offs[k] = off;
            off += cnt[k];
        }
        g_offs[b * 17 + 16] = off;
    }
    __syncthreads();
    if (threadIdx.x < KC) cnt[threadIdx.x] = offs[threadIdx.x];  // cursors
    __syncthreads();

    for (int n = threadIdx.x; n < HWN; n += 256) {
        int k = labels[b * HWN + n];
        unsigned mask = __match_any_sync(0xffffffffu, k);
        int leader = __ffs(mask) - 1;
        int rank = __popc(mask & ((1u << lane) - 1u));
        int base = 0;
        if (lane == leader) base = atomicAdd(&cnt[k], __popc(mask));
        base = __shfl_sync(0xffffffffu, base, leader);
        g_perm[b * HWN + base + rank] = n;
    }
}

// ================= K3: centers (coalesced reduction over perm) + fused MLPs =================
// grid 256 (= b*16+k), block 192 (each thread owns cols t, t+192, t+384)
__global__ void centers_mlp_kernel(const float* __restrict__ lr_w1, const float* __restrict__ lr_b1,
                                   const float* __restrict__ lr_w2, const float* __restrict__ lr_b2,
                                   const float* __restrict__ lr_w3, const float* __restrict__ lr_b3,
                                   const float* __restrict__ bw1,   const float* __restrict__ bb1,
                                   const float* __restrict__ bw2,   const float* __restrict__ bb2) {
    __shared__ float cs[FF];
    __shared__ float h1[MLPD], h2[MLPD], t1v[MLPD];
    const int bk = blockIdx.x;
    const int b = bk >> 4;
    const int off = g_offs[bk + b];
    const int end = g_offs[bk + b + 1];
    const int nk = end - off;
    const int t = threadIdx.x;
    const int pb = b << 12;
    const int* __restrict__ pm = g_perm + pb + off;

    float s0 = 0, s1 = 0, s2 = 0;
    float u0 = 0, u1 = 0, u2 = 0;
    float v0 = 0, v1 = 0, v2 = 0;
    float w0 = 0, w1 = 0, w2 = 0;
    int r = 0;
    for (; r + 4 <= nk; r += 4) {
        const float* p0 = g_patches + (size_t)(pb + pm[r + 0]) * FF;
        const float* p1 = g_patches + (size_t)(pb + pm[r + 1]) * FF;
        const float* p2 = g_patches + (size_t)(pb + pm[r + 2]) * FF;
        const float* p3 = g_patches + (size_t)(pb + pm[r + 3]) * FF;
        s0 += p0[t]; s1 += p0[t + 192]; s2 += p0[t + 384];
        u0 += p1[t]; u1 += p1[t + 192]; u2 += p1[t + 384];
        v0 += p2[t]; v1 += p2[t + 192]; v2 += p2[t + 384];
        w0 += p3[t]; w1 += p3[t + 192]; w2 += p3[t + 384];
    }
    for (; r < nk; r++) {
        const float* p0 = g_patches + (size_t)(pb + pm[r]) * FF;
        s0 += p0[t]; s1 += p0[t + 192]; s2 += p0[t + 384];
    }
    const float inv = 1.0f / ((float)nk + 1e-6f);
    cs[t]       = (s0 + u0 + v0 + w0) * inv;
    cs[t + 192] = (s1 + u1 + v1 + w1) * inv;
    cs[t + 384] = (s2 + u2 + v2 + w2) * inv;
    __syncthreads();

    const int j = t;
    if (j < MLPD) {
        float s = lr_b1[j];
        float s2x = bb1[j];
        for (int f = 0; f < FF; f++) {
            float cv = cs[f];
            s   += cv * lr_w1[f * MLPD + j];
            s2x += cv * bw1[f * MLPD + j];
        }
        h1[j]  = fmaxf(s, 0.f);
        t1v[j] = fmaxf(s2x, 0.f);
    }
    __syncthreads();
    if (j < MLPD) {
        float s = lr_b2[j];
        for (int i = 0; i < MLPD; i++) s += h1[i] * lr_w2[i * MLPD + j];
        h2[j] = fmaxf(s, 0.f);
    }
    __syncthreads();
    if (j < RR) {
        float s = lr_b3[j];
        for (int i = 0; i < MLPD; i++) s += h2[i] * lr_w3[i * RR + j];
        g_lowrank[bk * RR + j] = s;
    }
    if (j < OO) {
        float s = bb2[j];
        for (int i = 0; i < MLPD; i++) s += t1v[i] * bw2[i * OO + j];
        g_biasv[bk * OO + j] = s;
    }
}

// ================= K4: fabricate per-cluster kernels =================
// kernels[bk][f][o] = sum_r lowrank[bk][r] * base[r][f][o]
// grid (36 f-chunks of 16 rows, 8 bk-groups of 32), block 256
__global__ void buildk_kernel(const float* __restrict__ base) {
    __shared__ float bs[RR][16 * 64];   // 32 KB
    __shared__ float lrs[32][RR];
    const int fb = blockIdx.x, gb = blockIdx.y;
    const int f0 = fb * 16;

    for (int idx = threadIdx.x; idx < RR * 1024; idx += 256) {
        int r = idx >> 10;
        int e = idx & 1023;
        bs[r][e] = base[((size_t)(r * FF + f0 + (e >> 6))) * OO + (e & 63)];
    }
    for (int idx = threadIdx.x; idx < 32 * RR; idx += 256)
        lrs[idx >> 3][idx & 7] = g_lowrank[(gb * 32 + (idx >> 3)) * RR + (idx & 7)];
    __syncthreads();

    for (int bi = 0; bi < 32; bi++) {
        const int bk = gb * 32 + bi;
        float l[RR];
#pragma unroll
        for (int r = 0; r < RR; r++) l[r] = lrs[bi][r];
#pragma unroll
        for (int s = 0; s < 4; s++) {
            int e = threadIdx.x + (s << 8);
            float v = 0.f;
#pragma unroll
            for (int r = 0; r < RR; r++) v += l[r] * bs[r][e];
            g_kernels[(size_t)bk * (FF * OO) + f0 * OO + e] = v;
        }
    }
}

// ================= K5: grouped GEMM (fp32x2 packed FMA, conflict-free LDS) =================
// tile M=128, N=64, K chunks of 64. grid (256 bk, 16 m-tiles), block 256
// thread (tx=tid&7, ty=tid>>3): rows ty+{0,32,64,96}, cols tx*4+{0..3} and tx*4+32+{0..3}
// dyn smem: A[2][128][68] (69632 B) + B[2][64][64] (32768 B) + rows[128] (512 B) = 102912 B
__global__ void __launch_bounds__(256, 2) gemm_kernel(float* __restrict__ out) {
    extern __shared__ char smraw[];
    float* Asm = (float*)smraw;                        // stride 68 per row
    float* Bsm = (float*)(smraw + 69632);
    int*  rows = (int*)(smraw + 69632 + 32768);

    const int bk = blockIdx.x;
    const int b = bk >> 4;
    const int off = g_offs[bk + b];        // b*17 + k
    const int end = g_offs[bk + b + 1];
    const int m0 = blockIdx.y << 7;
    if (off + m0 >= end) return;
    const int nk = end - off;
    const int tid = threadIdx.x;

    if (tid < 128) {
        int i = m0 + tid;
        rows[tid] = g_perm[(b << 12) + off + (i < nk ? i : 0)];
    }
    __syncthreads();

    const float* __restrict__ pb = g_patches + ((size_t)b << 12) * FF;
    const float* __restrict__ kb = g_kernels + (size_t)bk * (FF * OO);

    unsigned long long acc[16];
#pragma unroll
    for (int i = 0; i < 16; i++) acc[i] = 0ull;

    const int tx = tid & 7, ty = tid >> 3;

    // prologue: chunk 0
    {
#pragma unroll
        for (int s = 0; s < 8; s++) {
            int cid = tid + (s << 8);
            int row = cid >> 4, seg = (cid & 15) << 2;
            CP16(smem_u32(Asm + row * 68 + seg), pb + (size_t)rows[row] * FF + seg);
        }
#pragma unroll
        for (int s = 0; s < 4; s++) {
            int cid = (tid + (s << 8)) << 2;
            CP16(smem_u32(Bsm + cid), kb + cid);
        }
        CP_COMMIT();
    }

    for (int c = 0; c < 9; c++) {
        const int buf = c & 1;
        if (c < 8) {
            const int nb = buf ^ 1;
            const int kc = (c + 1) << 6;
#pragma unroll
            for (int s = 0; s < 8; s++) {
                int cid = tid + (s << 8);
                int row = cid >> 4, seg = (cid & 15) << 2;
                CP16(smem_u32(Asm + nb * 8704 + row * 68 + seg),
                     pb + (size_t)rows[row] * FF + kc + seg);
            }
#pragma unroll
            for (int s = 0; s < 4; s++) {
                int cid = (tid + (s << 8)) << 2;
                CP16(smem_u32(Bsm + nb * 4096 + cid), kb + (size_t)kc * 64 + cid);
            }
            CP_COMMIT();
            CP_WAIT(1);
        } else {
            CP_WAIT(0);
        }
        __syncthreads();

        const float* Ab = Asm + buf * 8704 + ty * 68;   // rows ty + 32j -> + j*2176
        const float* Bb = Bsm + buf * 4096 + (tx << 2);
#pragma unroll 8
        for (int kk = 0; kk < 64; kk++) {
            unsigned long long pa[4];
            pa[0] = pack2(Ab[kk]);
            pa[1] = pack2(Ab[kk + 2176]);
            pa[2] = pack2(Ab[kk + 4352]);
            pa[3] = pack2(Ab[kk + 6528]);
            float4 f0 = *reinterpret_cast<const float4*>(Bb + (kk << 6));
            float4 f1 = *reinterpret_cast<const float4*>(Bb + (kk << 6) + 32);
            ulonglong2 q0 = *reinterpret_cast<const ulonglong2*>(&f0);
            ulonglong2 q1 = *reinterpret_cast<const ulonglong2*>(&f1);
            unsigned long long bbv[4] = {q0.x, q0.y, q1.x, q1.y};
#pragma unroll
            for (int j = 0; j < 4; j++) {
#pragma unroll
                for (int p = 0; p < 4; p++) {
                    FMA2(acc[(j << 2) + p], pa[j], bbv[p], acc[(j << 2) + p]);
                }
            }
        }
        __syncthreads();
    }

    // epilogue: add cluster bias, scatter to out[b][o][n]
    float bias[8];
#pragma unroll
    for (int q = 0; q < 8; q++)
        bias[q] = g_biasv[(bk << 6) + (tx << 2) + ((q >> 2) << 5) + (q & 3)];

#pragma unroll
    for (int j = 0; j < 4; j++) {
        int i = m0 + ty + (j << 5);
        if (i < nk) {
            int n = rows[ty + (j << 5)];
#pragma unroll
            for (int p = 0; p < 4; p++) {
                uint32_t lo, hi;
                asm("mov.b64 {%0,%1}, %2;" : "=r"(lo), "=r"(hi) : "l"(acc[(j << 2) + p]));
                int o = (tx << 2) + ((p >> 1) << 5) + ((p & 1) << 1);
                int bq = ((p >> 1) << 2) + ((p & 1) << 1);
                out[(size_t)((b << 6) + o) * HWN + n]     = __uint_as_float(lo) + bias[bq];
                out[(size_t)((b << 6) + o + 1) * HWN + n] = __uint_as_float(hi) + bias[bq + 1];
            }
        }
    }
}

// ================= launch =================
extern "C" void kernel_launch(void* const* d_in, const int* in_sizes, int n_in,
                              void* d_out, int out_size) {
    const float* x      = (const float*)d_in[0];
    const int*   labels = (const int*)d_in[1];
    const float* lr_w1  = (const float*)d_in[2];
    const float* lr_b1  = (const float*)d_in[3];
    const float* lr_w2  = (const float*)d_in[4];
    const float* lr_b2  = (const float*)d_in[5];
    const float* lr_w3  = (const float*)d_in[6];
    const float* lr_b3  = (const float*)d_in[7];
    const float* base   = (const float*)d_in[8];
    const float* bw1    = (const float*)d_in[9];
    const float* bb1    = (const float*)d_in[10];
    const float* bw2    = (const float*)d_in[11];
    const float* bb2    = (const float*)d_in[12];
    float* out = (float*)d_out;

    cudaFuncSetAttribute(unfold_kernel, cudaFuncAttributeMaxDynamicSharedMemorySize, 50176);
    cudaFuncSetAttribute(gemm_kernel,   cudaFuncAttributeMaxDynamicSharedMemorySize, 102912);

    unfold_kernel<<<dim3(64, 16), 256, 49920>>>(x);
    count_scatter_kernel<<<16, 256>>>(labels);
    centers_mlp_kernel<<<256, 192>>>(lr_w1, lr_b1, lr_w2, lr_b2, lr_w3, lr_b3,
                                     bw1, bb1, bw2, bb2);
    buildk_kernel<<<dim3(36, 8), 256>>>(base);
    gemm_kernel<<<dim3(256, 16), 256, 102912>>>(out);
}